// round 2
// baseline (speedup 1.0000x reference)
#include <cuda_runtime.h>
#include <cuda_bf16.h>

// RandomPool: out[b,c,i,j] = x[b,c, 2*i + sel/2, 2*j + sel%2]
// sel = select_idx[b/T, i*56+j], shared across C=128 channels and T=8 frames.
//
// Shapes (fixed):
//   x:          [32, 128, 112, 112] f32   (205.5 MB)
//   select_idx: [4, 3136] i32             (49 KB, L2-hot)
//   out:        [32, 128, 56, 56] f32     (51.4 MB)
//
// DRAM-bound gather. Each thread produces 4 consecutive output cols:
//  - loads BOTH candidate source rows' 8-float spans unconditionally
//    (4 independent float4 loads, addresses independent of sel -> MLP=5,
//    no dependent-load chain)
//  - loads 4 selection indices as one int4 (L2-hot)
//  - resolves dr/dc with register selects, stores one float4.

#define SIDE   56
#define NP     3136        // 56*56
#define PLANE  12544       // 112*112
#define J4     14          // SIDE / 4

__global__ void __launch_bounds__(256, 8) randpool_kernel(
    const float* __restrict__ x,
    const int*   __restrict__ sel,
    float*       __restrict__ out,
    int total4)
{
    int t = blockIdx.x * blockDim.x + threadIdx.x;
    if (t >= total4) return;

    // t -> (bc, i, jj): jj indexes groups of 4 output columns
    int jj   = t % J4;
    int rest = t / J4;
    int i    = rest % SIDE;
    int bc   = rest / SIDE;          // b*128 + c, 0..4095
    int clip = bc >> 10;             // (bc/128)/8

    // Independent loads: 4 sel indices + both source rows (8 floats each).
    const int4 s4 = *reinterpret_cast<const int4*>(
        sel + clip * NP + i * SIDE + 4 * jj);

    const float* rowbase = x + (size_t)bc * PLANE + i * 224 + 8 * jj;
    // row 2*i   : floats [0..7]   -> r0a, r0b
    // row 2*i+1 : floats [112..119] -> r1a, r1b
    const float4 r0a = *reinterpret_cast<const float4*>(rowbase);
    const float4 r0b = *reinterpret_cast<const float4*>(rowbase + 4);
    const float4 r1a = *reinterpret_cast<const float4*>(rowbase + 112);
    const float4 r1b = *reinterpret_cast<const float4*>(rowbase + 116);

    // out col j0+p uses source cols 2p, 2p+1 of row (s>>1); pick col by s&1.
    float4 r;
    {
        int s = s4.x;
        float a = (s & 2) ? r1a.x : r0a.x;
        float b = (s & 2) ? r1a.y : r0a.y;
        r.x = (s & 1) ? b : a;
    }
    {
        int s = s4.y;
        float a = (s & 2) ? r1a.z : r0a.z;
        float b = (s & 2) ? r1a.w : r0a.w;
        r.y = (s & 1) ? b : a;
    }
    {
        int s = s4.z;
        float a = (s & 2) ? r1b.x : r0b.x;
        float b = (s & 2) ? r1b.y : r0b.y;
        r.z = (s & 1) ? b : a;
    }
    {
        int s = s4.w;
        float a = (s & 2) ? r1b.z : r0b.z;
        float b = (s & 2) ? r1b.w : r0b.w;
        r.w = (s & 1) ? b : a;
    }

    // out float4 index == t (bc*3136 + i*56 + 4*jj = 4*t)
    reinterpret_cast<float4*>(out)[t] = r;
}

extern "C" void kernel_launch(void* const* d_in, const int* in_sizes, int n_in,
                              void* d_out, int out_size) {
    const float* x   = (const float*)d_in[0];
    const int*   sel = (const int*)d_in[1];
    float*       out = (float*)d_out;

    const int total4 = out_size / 4;          // 3,211,264
    const int threads = 256;
    const int blocks = (total4 + threads - 1) / threads;  // 12,544
    randpool_kernel<<<blocks, threads>>>(x, sel, out, total4);
}